// round 4
// baseline (speedup 1.0000x reference)
#include <cuda_runtime.h>
#include <cuda_bf16.h>
#include <cstdint>

// ---------------------------------------------------------------------------
// Problem constants
// ---------------------------------------------------------------------------
#define BB   16384
#define NE   32
#define EE   128
#define HH   256
#define TILE_M 256                 // supertile rows (M=32 per warp)
#define SUPERTILES 2               // 2 x 256 = 512 rows per CTA
#define GROUPS 32
#define NUM_CTAS (NE * GROUPS)

// SMEM pitches (bf16 elements)
#define PX  136
#define PW1 136
#define PW2 264

#define OFF_X   0
#define SZ_X    (TILE_M * PX * 2)             // 69632
#define OFF_W1  (OFF_X + SZ_X)
#define SZ_W1   (HH * PW1 * 2)                // 69632
#define OFF_W2  (OFF_W1 + SZ_W1)
#define SZ_W2   (EE * PW2 * 2)                // 67584
#define OFF_B1  (OFF_W2 + SZ_W2)
#define OFF_B2  (OFF_B1 + HH * 4)
#define OFF_RED (OFF_B2 + EE * 4)
#define SMEM_TOTAL (OFF_RED + 32 * 4)         // ~208.5 KB

// ---------------------------------------------------------------------------
// Base-ISA PTX helpers (harness front-end is sm_103: no 'a' features)
// ---------------------------------------------------------------------------
static __device__ __forceinline__ uint32_t smem_u32(const void* p) {
    uint32_t a;
    asm("{ .reg .u64 t; cvta.to.shared.u64 t, %1; cvt.u32.u64 %0, t; }"
        : "=r"(a) : "l"(p));
    return a;
}

#define LDSM4(r, addr)                                                        \
    asm volatile("ldmatrix.sync.aligned.m8n8.x4.shared.b16 {%0,%1,%2,%3}, [%4];" \
                 : "=r"((r)[0]), "=r"((r)[1]), "=r"((r)[2]), "=r"((r)[3])      \
                 : "r"(addr))

#define MMA16816(c, a, b0, b1)                                                \
    asm volatile(                                                             \
        "mma.sync.aligned.m16n8k16.row.col.f32.bf16.bf16.f32 "                \
        "{%0,%1,%2,%3},{%4,%5,%6,%7},{%8,%9},{%0,%1,%2,%3};"                  \
        : "+f"((c)[0]), "+f"((c)[1]), "+f"((c)[2]), "+f"((c)[3])              \
        : "r"((a)[0]), "r"((a)[1]), "r"((a)[2]), "r"((a)[3]),                 \
          "r"(b0), "r"(b1))

// ---------------------------------------------------------------------------
static __device__ __forceinline__ float gelu_fast(float x) {
    float u = x * (0.7978845608f + 0.0356774081f * x * x);
    float t;
    asm("tanh.approx.f32 %0, %1;" : "=f"(t) : "f"(u));
    return 0.5f * x * (1.0f + t);
}

static __device__ __forceinline__ uint32_t packbf2(float lo, float hi) {
    __nv_bfloat162 p = __floats2bfloat162_rn(lo, hi);
    return *reinterpret_cast<uint32_t*>(&p);
}

__global__ void init_out_kernel(float* __restrict__ out) {
    out[0] = 0.0f;
}

__global__ __launch_bounds__(256, 1)
void distill_kernel(const float* __restrict__ feat, const float* __restrict__ tgt,
                    const float* __restrict__ W1g, const float* __restrict__ b1g,
                    const float* __restrict__ W2g, const float* __restrict__ b2g,
                    float* __restrict__ out) {
    extern __shared__ char smem[];
    const uint32_t sb  = smem_u32(smem);
    const int tid = threadIdx.x;
    const int wid = tid >> 5;
    const int lid = tid & 31;
    const int l4  = lid >> 2;
    const int lc2 = (lid & 3) * 2;
    const int n   = blockIdx.x;
    const int grp = blockIdx.y;

    float* b1s = (float*)(smem + OFF_B1);
    float* b2s = (float*)(smem + OFF_B2);

    // ---- one-time: weights fp32 -> bf16, transposed into SMEM ----
    {
        const float* w1 = W1g + (size_t)n * EE * HH;     // [k=128][h=256]
        #pragma unroll 4
        for (int f = tid; f < (EE * HH) / 4; f += 256) {
            int k  = f >> 6;
            int h4 = (f & 63) * 4;
            float4 v = *(const float4*)(w1 + k * HH + h4);
            __nv_bfloat16* base = (__nv_bfloat16*)(smem + OFF_W1) + k;
            base[(size_t)(h4 + 0) * PW1] = __float2bfloat16(v.x);
            base[(size_t)(h4 + 1) * PW1] = __float2bfloat16(v.y);
            base[(size_t)(h4 + 2) * PW1] = __float2bfloat16(v.z);
            base[(size_t)(h4 + 3) * PW1] = __float2bfloat16(v.w);
        }
        const float* w2 = W2g + (size_t)n * HH * EE;     // [h=256][e=128]
        #pragma unroll 4
        for (int f = tid; f < (HH * EE) / 4; f += 256) {
            int h  = f >> 5;
            int e4 = (f & 31) * 4;
            float4 v = *(const float4*)(w2 + h * EE + e4);
            __nv_bfloat16* base = (__nv_bfloat16*)(smem + OFF_W2) + h;
            base[(size_t)(e4 + 0) * PW2] = __float2bfloat16(v.x);
            base[(size_t)(e4 + 1) * PW2] = __float2bfloat16(v.y);
            base[(size_t)(e4 + 2) * PW2] = __float2bfloat16(v.z);
            base[(size_t)(e4 + 3) * PW2] = __float2bfloat16(v.w);
        }
        b1s[tid] = b1g[n * HH + tid];
        if (tid < EE) b2s[tid] = b2g[n * EE + tid];
    }

    // ---- stage X for supertile 0 (fp32 -> bf16, 256 rows) ----
    {
        const int row0  = tid >> 5;
        const int col4  = (tid & 31) * 4;
        const int rowbase = grp * (SUPERTILES * TILE_M);
        const float* gp = feat + ((size_t)(rowbase + row0) * NE + n) * EE + col4;
        char* sp = smem + OFF_X + (size_t)(row0 * PX + col4) * 2;
        #pragma unroll
        for (int it = 0; it < 32; it++) {
            float4 v = *(const float4*)(gp + (size_t)it * 8 * NE * EE);
            uint2 u;
            u.x = packbf2(v.x, v.y);
            u.y = packbf2(v.z, v.w);
            *reinterpret_cast<uint2*>(sp + (size_t)it * 8 * PX * 2) = u;
        }
    }
    __syncthreads();

    // per-lane ldmatrix address components (warp owns rows 32*wid..+31)
    const uint32_t xlane = sb + OFF_X +
        (uint32_t)(((32 * wid + (lid & 15)) * PX + 8 * (lid >> 4)) * 2);
    const uint32_t w1lane = sb + OFF_W1 +
        (uint32_t)((((lid & 7) + 8 * (lid >> 4)) * PW1 + 8 * ((lid >> 3) & 1)) * 2);
    const uint32_t w2lane = sb + OFF_W2 +
        (uint32_t)((((lid & 7) + 8 * (lid >> 4)) * PW2 + 8 * ((lid >> 3) & 1)) * 2);

    float acc = 0.0f;

    #pragma unroll 1
    for (int st = 0; st < SUPERTILES; st++) {
        const int rowbase = grp * (SUPERTILES * TILE_M) + st * TILE_M;

        // ---- load this warp's X fragments once (2 m16 blocks x 8 k16) ----
        uint32_t xf[2][8][4];
        #pragma unroll
        for (int mb = 0; mb < 2; mb++)
            #pragma unroll
            for (int s = 0; s < 8; s++)
                LDSM4(xf[mb][s], xlane + (uint32_t)((16 * mb * PX + 16 * s) * 2));

        float c2[2][16][4];
        #pragma unroll
        for (int mb = 0; mb < 2; mb++)
            #pragma unroll
            for (int i = 0; i < 16; i++)
                c2[mb][i][0] = c2[mb][i][1] = c2[mb][i][2] = c2[mb][i][3] = 0.f;

        #pragma unroll 1
        for (int ck = 0; ck < 8; ck++) {            // 32 h-cols per chunk
            // ---- GEMM1 chunk: C1[32 x 32] ----
            float c1[2][4][4];
            #pragma unroll
            for (int mb = 0; mb < 2; mb++)
                #pragma unroll
                for (int i = 0; i < 4; i++)
                    c1[mb][i][0] = c1[mb][i][1] = c1[mb][i][2] = c1[mb][i][3] = 0.f;

            #pragma unroll
            for (int s = 0; s < 8; s++) {
                #pragma unroll
                for (int jp = 0; jp < 2; jp++) {    // 16 h-cols per LDSM
                    uint32_t b[4];
                    LDSM4(b, w1lane +
                          (uint32_t)(((32 * ck + 16 * jp) * PW1 + 16 * s) * 2));
                    MMA16816(c1[0][2 * jp],     xf[0][s], b[0], b[1]);
                    MMA16816(c1[0][2 * jp + 1], xf[0][s], b[2], b[3]);
                    MMA16816(c1[1][2 * jp],     xf[1][s], b[0], b[1]);
                    MMA16816(c1[1][2 * jp + 1], xf[1][s], b[2], b[3]);
                }
            }

            // ---- bias + GELU -> GEMM2 A-fragments (register handoff) ----
            uint32_t A2[2][2][4];
            #pragma unroll
            for (int mb = 0; mb < 2; mb++) {
                #pragma unroll
                for (int j = 0; j < 4; j++) {
                    const float bb0 = b1s[32 * ck + 8 * j + lc2];
                    const float bb1 = b1s[32 * ck + 8 * j + lc2 + 1];
                    float v0 = gelu_fast(c1[mb][j][0] + bb0);
                    float v1 = gelu_fast(c1[mb][j][1] + bb1);
                    float v2 = gelu_fast(c1[mb][j][2] + bb0);
                    float v3 = gelu_fast(c1[mb][j][3] + bb1);
                    A2[mb][j >> 1][(j & 1) * 2 + 0] = packbf2(v0, v1);
                    A2[mb][j >> 1][(j & 1) * 2 + 1] = packbf2(v2, v3);
                }
            }

            // ---- GEMM2 partial: C2 += H_chunk[32 x 32] * W2[chunk, :] ----
            #pragma unroll
            for (int kb = 0; kb < 2; kb++) {
                #pragma unroll
                for (int tp = 0; tp < 8; tp++) {
                    uint32_t b[4];
                    LDSM4(b, w2lane +
                          (uint32_t)((16 * tp * PW2 + 32 * ck + 16 * kb) * 2));
                    MMA16816(c2[0][2 * tp],     A2[0][kb], b[0], b[1]);
                    MMA16816(c2[0][2 * tp + 1], A2[0][kb], b[2], b[3]);
                    MMA16816(c2[1][2 * tp],     A2[1][kb], b[0], b[1]);
                    MMA16816(c2[1][2 * tp + 1], A2[1][kb], b[2], b[3]);
                }
            }
        }

        __syncthreads();   // all warps done reading X smem

        // ---- overlap: stage next supertile's X before the epilogue ----
        if (st == 0) {
            const int row0  = tid >> 5;
            const int col4  = (tid & 31) * 4;
            const float* gp = feat +
                ((size_t)(rowbase + TILE_M + row0) * NE + n) * EE + col4;
            char* sp = smem + OFF_X + (size_t)(row0 * PX + col4) * 2;
            #pragma unroll
            for (int it = 0; it < 32; it++) {
                float4 v = *(const float4*)(gp + (size_t)it * 8 * NE * EE);
                uint2 u;
                u.x = packbf2(v.x, v.y);
                u.y = packbf2(v.z, v.w);
                *reinterpret_cast<uint2*>(sp + (size_t)it * 8 * PX * 2) = u;
            }
        }

        // ---- MSE epilogue (targets exact fp32 from GMEM) ----
        #pragma unroll
        for (int mb = 0; mb < 2; mb++) {
            const int r0 = rowbase + 32 * wid + 16 * mb + l4;
            const float* tg0 = tgt + ((size_t)r0 * NE + n) * EE;
            const float* tg1 = tg0 + (size_t)8 * NE * EE;
            #pragma unroll
            for (int tp = 0; tp < 16; tp++) {
                const int e = 8 * tp + lc2;
                const float bb0 = b2s[e], bb1 = b2s[e + 1];
                float2 t0 = *(const float2*)(tg0 + e);
                float2 t1 = *(const float2*)(tg1 + e);
                float d0 = c2[mb][tp][0] + bb0 - t0.x;
                float d1 = c2[mb][tp][1] + bb1 - t0.y;
                float d2 = c2[mb][tp][2] + bb0 - t1.x;
                float d3 = c2[mb][tp][3] + bb1 - t1.y;
                acc += d0 * d0 + d1 * d1 + d2 * d2 + d3 * d3;
            }
        }

        __syncthreads();   // staged X visible before next supertile's LDSM
    }

    // ---- block reduction -> scaled atomic into d_out ----
    #pragma unroll
    for (int o = 16; o > 0; o >>= 1) acc += __shfl_down_sync(0xffffffffu, acc, o);
    float* red = (float*)(smem + OFF_RED);
    if (lid == 0) red[wid] = acc;
    __syncthreads();
    if (tid == 0) {
        float s = 0.f;
        #pragma unroll
        for (int i = 0; i < 8; i++) s += red[i];
        atomicAdd(out, s * (1.0f / 67108864.0f));   // / (B*NE*E)
    }
}

extern "C" void kernel_launch(void* const* d_in, const int* in_sizes, int n_in,
                              void* d_out, int out_size) {
    (void)in_sizes; (void)n_in; (void)out_size;
    const float* feat = (const float*)d_in[0];
    const float* tgt  = (const float*)d_in[1];
    const float* W1   = (const float*)d_in[2];
    const float* b1   = (const float*)d_in[3];
    const float* W2   = (const float*)d_in[4];
    const float* b2   = (const float*)d_in[5];

    cudaFuncSetAttribute(distill_kernel,
                         cudaFuncAttributeMaxDynamicSharedMemorySize, SMEM_TOTAL);
    init_out_kernel<<<1, 1>>>((float*)d_out);
    dim3 grid(NE, GROUPS);
    distill_kernel<<<grid, 256, SMEM_TOTAL>>>(feat, tgt, W1, b1, W2, b2,
                                              (float*)d_out);
}

// round 5
// speedup vs baseline: 1.3565x; 1.3565x over previous
#include <cuda_runtime.h>
#include <cuda_bf16.h>
#include <cstdint>

// ---------------------------------------------------------------------------
// Problem constants
// ---------------------------------------------------------------------------
#define BB   16384
#define NE   32
#define EE   128
#define HH   256
#define TILE_M 128
#define TILES_PER_CTA 4
#define GROUPS 32
#define NUM_CTAS (NE * GROUPS)

// SMEM pitches (bf16 elements). 264*2=528B = 33*16B (odd multiple: conflict-free
// ldmatrix); 136*2=272B = 17*16B.
#define PB  264              // shared X/H buffer pitch (256 cols + pad)
#define PW1 136              // W1 [h][k] pitch (128 cols + pad)
#define PW2 264              // W2 [e][h] pitch (256 cols + pad)

#define OFF_BUF 0
#define SZ_BUF  (TILE_M * PB * 2)             // 67584  (X cols 0:128, later H 0:256)
#define OFF_W1  (OFF_BUF + SZ_BUF)
#define SZ_W1   (HH * PW1 * 2)                // 69632
#define OFF_W2  (OFF_W1 + SZ_W1)
#define SZ_W2   (EE * PW2 * 2)                // 67584
#define OFF_B1  (OFF_W2 + SZ_W2)
#define OFF_B2  (OFF_B1 + HH * 4)
#define OFF_RED (OFF_B2 + EE * 4)
#define SMEM_TOTAL (OFF_RED + 32 * 4)         // ~206.5 KB

// ---------------------------------------------------------------------------
// Base-ISA PTX helpers (harness front-end is sm_103: no 'a' features)
// ---------------------------------------------------------------------------
static __device__ __forceinline__ uint32_t smem_u32(const void* p) {
    uint32_t a;
    asm("{ .reg .u64 t; cvta.to.shared.u64 t, %1; cvt.u32.u64 %0, t; }"
        : "=r"(a) : "l"(p));
    return a;
}

#define LDSM4(r, addr)                                                        \
    asm volatile("ldmatrix.sync.aligned.m8n8.x4.shared.b16 {%0,%1,%2,%3}, [%4];" \
                 : "=r"((r)[0]), "=r"((r)[1]), "=r"((r)[2]), "=r"((r)[3])      \
                 : "r"(addr))

#define MMA16816(c, a, b0, b1)                                                \
    asm volatile(                                                             \
        "mma.sync.aligned.m16n8k16.row.col.f32.bf16.bf16.f32 "                \
        "{%0,%1,%2,%3},{%4,%5,%6,%7},{%8,%9},{%0,%1,%2,%3};"                  \
        : "+f"((c)[0]), "+f"((c)[1]), "+f"((c)[2]), "+f"((c)[3])              \
        : "r"((a)[0]), "r"((a)[1]), "r"((a)[2]), "r"((a)[3]),                 \
          "r"(b0), "r"(b1))

// ---------------------------------------------------------------------------
static __device__ __forceinline__ float gelu_fast(float x) {
    float u = x * (0.7978845608f + 0.0356774081f * x * x);
    float t;
    asm("tanh.approx.f32 %0, %1;" : "=f"(t) : "f"(u));
    return 0.5f * x * (1.0f + t);
}

static __device__ __forceinline__ uint32_t packbf2(float lo, float hi) {
    __nv_bfloat162 p = __floats2bfloat162_rn(lo, hi);
    return *reinterpret_cast<uint32_t*>(&p);
}

__global__ void init_out_kernel(float* __restrict__ out) {
    out[0] = 0.0f;
}

__global__ __launch_bounds__(256, 1)
void distill_kernel(const float* __restrict__ feat, const float* __restrict__ tgt,
                    const float* __restrict__ W1g, const float* __restrict__ b1g,
                    const float* __restrict__ W2g, const float* __restrict__ b2g,
                    float* __restrict__ out) {
    extern __shared__ char smem[];
    const uint32_t sb  = smem_u32(smem);
    const int tid = threadIdx.x;
    const int wid = tid >> 5;
    const int lid = tid & 31;
    const int m   = wid >> 1;           // M-group: rows 32m..32m+31
    const int p   = wid & 1;            // h-half (GEMM1 N) and e-half (GEMM2 N)
    const int l4  = lid >> 2;
    const int lc2 = (lid & 3) * 2;
    const int n   = blockIdx.x;
    const int grp = blockIdx.y;

    float* b1s = (float*)(smem + OFF_B1);
    float* b2s = (float*)(smem + OFF_B2);

    // ---- one-time: weights fp32 -> bf16, transposed into SMEM ----
    {
        const float* w1 = W1g + (size_t)n * EE * HH;     // [k=128][h=256]
        #pragma unroll 4
        for (int f = tid; f < (EE * HH) / 4; f += 256) {
            int k  = f >> 6;
            int h4 = (f & 63) * 4;
            float4 v = *(const float4*)(w1 + k * HH + h4);
            __nv_bfloat16* base = (__nv_bfloat16*)(smem + OFF_W1) + k;
            base[(size_t)(h4 + 0) * PW1] = __float2bfloat16(v.x);
            base[(size_t)(h4 + 1) * PW1] = __float2bfloat16(v.y);
            base[(size_t)(h4 + 2) * PW1] = __float2bfloat16(v.z);
            base[(size_t)(h4 + 3) * PW1] = __float2bfloat16(v.w);
        }
        const float* w2 = W2g + (size_t)n * HH * EE;     // [h=256][e=128]
        #pragma unroll 4
        for (int f = tid; f < (HH * EE) / 4; f += 256) {
            int h  = f >> 5;
            int e4 = (f & 31) * 4;
            float4 v = *(const float4*)(w2 + h * EE + e4);
            __nv_bfloat16* base = (__nv_bfloat16*)(smem + OFF_W2) + h;
            base[(size_t)(e4 + 0) * PW2] = __float2bfloat16(v.x);
            base[(size_t)(e4 + 1) * PW2] = __float2bfloat16(v.y);
            base[(size_t)(e4 + 2) * PW2] = __float2bfloat16(v.z);
            base[(size_t)(e4 + 3) * PW2] = __float2bfloat16(v.w);
        }
        b1s[tid] = b1g[n * HH + tid];
        if (tid < EE) b2s[tid] = b2g[n * EE + tid];
    }

    // per-lane ldmatrix base addresses
    const uint32_t xlane = sb + OFF_BUF +                 // A frags (X then H)
        (uint32_t)(((32 * m + (lid & 15)) * PB + 8 * (lid >> 4)) * 2);
    const uint32_t w1lane = sb + OFF_W1 +
        (uint32_t)((((lid & 7) + 8 * (lid >> 4)) * PW1 + 8 * ((lid >> 3) & 1)) * 2);
    const uint32_t w2lane = sb + OFF_W2 +
        (uint32_t)((((lid & 7) + 8 * (lid >> 4)) * PW2 + 8 * ((lid >> 3) & 1)) * 2);

    float acc = 0.0f;

    #pragma unroll 1
    for (int t = 0; t < TILES_PER_CTA; t++) {
        const int rowbase = grp * (TILES_PER_CTA * TILE_M) + t * TILE_M;
        __syncthreads();   // buffer free (prev tile's H reads done)

        // ---- stage X tile: fp32 GMEM -> bf16 buffer cols 0:128 ----
        {
            const int row0  = tid >> 5;
            const int col4  = (tid & 31) * 4;
            const float* gp = feat + ((size_t)(rowbase + row0) * NE + n) * EE + col4;
            char* sp = smem + OFF_BUF + (size_t)(row0 * PB + col4) * 2;
            #pragma unroll
            for (int it = 0; it < 16; it++) {
                float4 v = *(const float4*)(gp + (size_t)it * 8 * NE * EE);
                uint2 u;
                u.x = packbf2(v.x, v.y);
                u.y = packbf2(v.z, v.w);
                *reinterpret_cast<uint2*>(sp + (size_t)it * 8 * PB * 2) = u;
            }
        }
        __syncthreads();

        // ---- cache this warp's X fragments (2 m16 x 8 k16 = 64 regs) ----
        uint32_t xf[2][8][4];
        #pragma unroll
        for (int mb = 0; mb < 2; mb++)
            #pragma unroll
            for (int s = 0; s < 8; s++)
                LDSM4(xf[mb][s], xlane + (uint32_t)((16 * mb * PB + 16 * s) * 2));

        // ---- GEMM1 (N = this warp's h-half, chunked 32 cols) + GELU + keep A2 ----
        uint32_t A2s[4][2][2][4];   // [ck][mb][kb][4] bf16x2 frags, 64 regs
        #pragma unroll 1
        for (int ck = 0; ck < 4; ck++) {
            float c1[2][4][4];
            #pragma unroll
            for (int mb = 0; mb < 2; mb++)
                #pragma unroll
                for (int i = 0; i < 4; i++)
                    c1[mb][i][0] = c1[mb][i][1] = c1[mb][i][2] = c1[mb][i][3] = 0.f;

            #pragma unroll
            for (int s = 0; s < 8; s++) {
                #pragma unroll
                for (int jp = 0; jp < 2; jp++) {
                    uint32_t b[4];
                    LDSM4(b, w1lane + (uint32_t)(((p * 128 + ck * 32 + 16 * jp) * PW1
                                                  + 16 * s) * 2));
                    MMA16816(c1[0][2 * jp],     xf[0][s], b[0], b[1]);
                    MMA16816(c1[0][2 * jp + 1], xf[0][s], b[2], b[3]);
                    MMA16816(c1[1][2 * jp],     xf[1][s], b[0], b[1]);
                    MMA16816(c1[1][2 * jp + 1], xf[1][s], b[2], b[3]);
                }
            }

            #pragma unroll
            for (int mb = 0; mb < 2; mb++) {
                #pragma unroll
                for (int j = 0; j < 4; j++) {
                    const float bb0 = b1s[p * 128 + ck * 32 + 8 * j + lc2];
                    const float bb1 = b1s[p * 128 + ck * 32 + 8 * j + lc2 + 1];
                    float v0 = gelu_fast(c1[mb][j][0] + bb0);
                    float v1 = gelu_fast(c1[mb][j][1] + bb1);
                    float v2 = gelu_fast(c1[mb][j][2] + bb0);
                    float v3 = gelu_fast(c1[mb][j][3] + bb1);
                    A2s[ck][mb][j >> 1][(j & 1) * 2 + 0] = packbf2(v0, v1);
                    A2s[ck][mb][j >> 1][(j & 1) * 2 + 1] = packbf2(v2, v3);
                }
            }
        }

        __syncthreads();   // all warps done reading X from buffer

        // ---- STS: A2 -> H in buffer (rows 32m.., cols p*128 + ...) ----
        #pragma unroll
        for (int ck = 0; ck < 4; ck++) {
            #pragma unroll
            for (int mb = 0; mb < 2; mb++) {
                const int r0 = 32 * m + 16 * mb + l4;
                #pragma unroll
                for (int kb = 0; kb < 2; kb++) {
                    const int c0 = p * 128 + ck * 32 + 16 * kb + lc2;
                    *(uint32_t*)(smem + OFF_BUF + (size_t)(r0 * PB + c0) * 2)
                        = A2s[ck][mb][kb][0];
                    *(uint32_t*)(smem + OFF_BUF + (size_t)(r0 * PB + c0 + 8) * 2)
                        = A2s[ck][mb][kb][1];
                    *(uint32_t*)(smem + OFF_BUF + (size_t)((r0 + 8) * PB + c0) * 2)
                        = A2s[ck][mb][kb][2];
                    *(uint32_t*)(smem + OFF_BUF + (size_t)((r0 + 8) * PB + c0 + 8) * 2)
                        = A2s[ck][mb][kb][3];
                }
            }
        }
        __syncthreads();   // H complete

        // ---- GEMM2: C2[32 x 64] (e-half p), K = 256 via H LDSM ----
        float c2[2][8][4];
        #pragma unroll
        for (int mb = 0; mb < 2; mb++)
            #pragma unroll
            for (int i = 0; i < 8; i++)
                c2[mb][i][0] = c2[mb][i][1] = c2[mb][i][2] = c2[mb][i][3] = 0.f;

        #pragma unroll
        for (int s = 0; s < 16; s++) {
            uint32_t a0[4], a1[4];
            LDSM4(a0, xlane + (uint32_t)((16 * s) * 2));
            LDSM4(a1, xlane + (uint32_t)((16 * PB + 16 * s) * 2));
            #pragma unroll
            for (int tp = 0; tp < 4; tp++) {
                uint32_t b[4];
                LDSM4(b, w2lane + (uint32_t)(((p * 64 + 16 * tp) * PW2 + 16 * s) * 2));
                MMA16816(c2[0][2 * tp],     a0, b[0], b[1]);
                MMA16816(c2[0][2 * tp + 1], a0, b[2], b[3]);
                MMA16816(c2[1][2 * tp],     a1, b[0], b[1]);
                MMA16816(c2[1][2 * tp + 1], a1, b[2], b[3]);
            }
        }

        // ---- MSE epilogue (targets exact fp32 from GMEM) ----
        #pragma unroll
        for (int mb = 0; mb < 2; mb++) {
            const int r0 = rowbase + 32 * m + 16 * mb + l4;
            const float* tg0 = tgt + ((size_t)r0 * NE + n) * EE;
            const float* tg1 = tg0 + (size_t)8 * NE * EE;
            #pragma unroll
            for (int tp = 0; tp < 8; tp++) {
                const int e = p * 64 + 8 * tp + lc2;
                const float bb0 = b2s[e], bb1 = b2s[e + 1];
                float2 t0 = *(const float2*)(tg0 + e);
                float2 t1 = *(const float2*)(tg1 + e);
                float d0 = c2[mb][tp][0] + bb0 - t0.x;
                float d1 = c2[mb][tp][1] + bb1 - t0.y;
                float d2 = c2[mb][tp][2] + bb0 - t1.x;
                float d3 = c2[mb][tp][3] + bb1 - t1.y;
                acc += d0 * d0 + d1 * d1 + d2 * d2 + d3 * d3;
            }
        }
    }

    // ---- block reduction -> scaled atomic into d_out ----
    #pragma unroll
    for (int o = 16; o > 0; o >>= 1) acc += __shfl_down_sync(0xffffffffu, acc, o);
    float* red = (float*)(smem + OFF_RED);
    __syncthreads();
    if (lid == 0) red[wid] = acc;
    __syncthreads();
    if (tid == 0) {
        float s = 0.f;
        #pragma unroll
        for (int i = 0; i < 8; i++) s += red[i];
        atomicAdd(out, s * (1.0f / 67108864.0f));   // / (B*NE*E)
    }
}

extern "C" void kernel_launch(void* const* d_in, const int* in_sizes, int n_in,
                              void* d_out, int out_size) {
    (void)in_sizes; (void)n_in; (void)out_size;
    const float* feat = (const float*)d_in[0];
    const float* tgt  = (const float*)d_in[1];
    const float* W1   = (const float*)d_in[2];
    const float* b1   = (const float*)d_in[3];
    const float* W2   = (const float*)d_in[4];
    const float* b2   = (const float*)d_in[5];

    cudaFuncSetAttribute(distill_kernel,
                         cudaFuncAttributeMaxDynamicSharedMemorySize, SMEM_TOTAL);
    init_out_kernel<<<1, 1>>>((float*)d_out);
    dim3 grid(NE, GROUPS);
    distill_kernel<<<grid, 256, SMEM_TOTAL>>>(feat, tgt, W1, b1, W2, b2,
                                              (float*)d_out);
}

// round 6
// speedup vs baseline: 1.4252x; 1.0506x over previous
#include <cuda_runtime.h>
#include <cuda_bf16.h>
#include <cstdint>

// ---------------------------------------------------------------------------
// Problem constants
// ---------------------------------------------------------------------------
#define BB   16384
#define NE   32
#define EE   128
#define HH   256
#define TILE_M 256                 // 16 warps x M=16
#define TILES_PER_CTA 2
#define GROUPS 32
#define NTHREADS 512

// SMEM pitches (bf16 elements); x*2 bytes = odd multiple of 16B -> conflict-free
#define PX  136
#define PW1 136
#define PW2 264

#define OFF_X   0
#define SZ_X    (TILE_M * PX * 2)             // 69632
#define OFF_W1  (OFF_X + SZ_X)
#define SZ_W1   (HH * PW1 * 2)                // 69632
#define OFF_W2  (OFF_W1 + SZ_W1)
#define SZ_W2   (EE * PW2 * 2)                // 67584
#define OFF_B1  (OFF_W2 + SZ_W2)
#define OFF_B2  (OFF_B1 + HH * 4)
#define OFF_RED (OFF_B2 + EE * 4)
#define SMEM_TOTAL (OFF_RED + 16 * 4)         // ~208.5 KB

// ---------------------------------------------------------------------------
// Base-ISA PTX helpers (harness front-end is sm_103: no 'a' features)
// ---------------------------------------------------------------------------
static __device__ __forceinline__ uint32_t smem_u32(const void* p) {
    uint32_t a;
    asm("{ .reg .u64 t; cvta.to.shared.u64 t, %1; cvt.u32.u64 %0, t; }"
        : "=r"(a) : "l"(p));
    return a;
}

#define LDSM4(r, addr)                                                        \
    asm volatile("ldmatrix.sync.aligned.m8n8.x4.shared.b16 {%0,%1,%2,%3}, [%4];" \
                 : "=r"((r)[0]), "=r"((r)[1]), "=r"((r)[2]), "=r"((r)[3])      \
                 : "r"(addr))

#define MMA16816(c, a, b0, b1)                                                \
    asm volatile(                                                             \
        "mma.sync.aligned.m16n8k16.row.col.f32.bf16.bf16.f32 "                \
        "{%0,%1,%2,%3},{%4,%5,%6,%7},{%8,%9},{%0,%1,%2,%3};"                  \
        : "+f"((c)[0]), "+f"((c)[1]), "+f"((c)[2]), "+f"((c)[3])              \
        : "r"((a)[0]), "r"((a)[1]), "r"((a)[2]), "r"((a)[3]),                 \
          "r"(b0), "r"(b1))

// ---------------------------------------------------------------------------
static __device__ __forceinline__ float gelu_fast(float x) {
    float u = x * (0.7978845608f + 0.0356774081f * x * x);
    float t;
    asm("tanh.approx.f32 %0, %1;" : "=f"(t) : "f"(u));
    return 0.5f * x * (1.0f + t);
}

static __device__ __forceinline__ uint32_t packbf2(float lo, float hi) {
    __nv_bfloat162 p = __floats2bfloat162_rn(lo, hi);
    return *reinterpret_cast<uint32_t*>(&p);
}

__global__ void init_out_kernel(float* __restrict__ out) {
    out[0] = 0.0f;
}

__global__ __launch_bounds__(NTHREADS, 1)
void distill_kernel(const float* __restrict__ feat, const float* __restrict__ tgt,
                    const float* __restrict__ W1g, const float* __restrict__ b1g,
                    const float* __restrict__ W2g, const float* __restrict__ b2g,
                    float* __restrict__ out) {
    extern __shared__ char smem[];
    const uint32_t sb  = smem_u32(smem);
    const int tid = threadIdx.x;
    const int wid = tid >> 5;           // 0..15, warp owns rows 16*wid..+15
    const int lid = tid & 31;
    const int l4  = lid >> 2;
    const int lc2 = (lid & 3) * 2;
    const int n   = blockIdx.x;
    const int grp = blockIdx.y;

    float* b1s = (float*)(smem + OFF_B1);
    float* b2s = (float*)(smem + OFF_B2);

    // ---- one-time: weights fp32 -> bf16, transposed into SMEM ----
    {
        const float* w1 = W1g + (size_t)n * EE * HH;     // [k=128][h=256]
        #pragma unroll 4
        for (int f = tid; f < (EE * HH) / 4; f += NTHREADS) {
            int k  = f >> 6;
            int h4 = (f & 63) * 4;
            float4 v = *(const float4*)(w1 + k * HH + h4);
            __nv_bfloat16* base = (__nv_bfloat16*)(smem + OFF_W1) + k;
            base[(size_t)(h4 + 0) * PW1] = __float2bfloat16(v.x);
            base[(size_t)(h4 + 1) * PW1] = __float2bfloat16(v.y);
            base[(size_t)(h4 + 2) * PW1] = __float2bfloat16(v.z);
            base[(size_t)(h4 + 3) * PW1] = __float2bfloat16(v.w);
        }
        const float* w2 = W2g + (size_t)n * HH * EE;     // [h=256][e=128]
        #pragma unroll 4
        for (int f = tid; f < (HH * EE) / 4; f += NTHREADS) {
            int h  = f >> 5;
            int e4 = (f & 31) * 4;
            float4 v = *(const float4*)(w2 + h * EE + e4);
            __nv_bfloat16* base = (__nv_bfloat16*)(smem + OFF_W2) + h;
            base[(size_t)(e4 + 0) * PW2] = __float2bfloat16(v.x);
            base[(size_t)(e4 + 1) * PW2] = __float2bfloat16(v.y);
            base[(size_t)(e4 + 2) * PW2] = __float2bfloat16(v.z);
            base[(size_t)(e4 + 3) * PW2] = __float2bfloat16(v.w);
        }
        if (tid < HH) b1s[tid] = b1g[n * HH + tid];
        if (tid < EE) b2s[tid] = b2g[n * EE + tid];
    }

    // ---- stage X for tile 0 ----
    {
        const int row0 = tid >> 5;               // 0..15
        const int col4 = (tid & 31) * 4;
        const int rowbase = grp * (TILES_PER_CTA * TILE_M);
        const float* gp = feat + ((size_t)(rowbase + row0) * NE + n) * EE + col4;
        char* sp = smem + OFF_X + (size_t)(row0 * PX + col4) * 2;
        #pragma unroll 8
        for (int it = 0; it < 16; it++) {        // rows row0 + 16*it
            float4 v = *(const float4*)(gp + (size_t)it * 16 * NE * EE);
            uint2 u;
            u.x = packbf2(v.x, v.y);
            u.y = packbf2(v.z, v.w);
            *reinterpret_cast<uint2*>(sp + (size_t)it * 16 * PX * 2) = u;
        }
    }
    __syncthreads();

    // per-lane ldmatrix base addresses
    const uint32_t xlane = sb + OFF_X +
        (uint32_t)(((16 * wid + (lid & 15)) * PX + 8 * (lid >> 4)) * 2);
    const uint32_t w1lane = sb + OFF_W1 +
        (uint32_t)((((lid & 7) + 8 * (lid >> 4)) * PW1 + 8 * ((lid >> 3) & 1)) * 2);
    const uint32_t w2lane = sb + OFF_W2 +
        (uint32_t)((((lid & 7) + 8 * (lid >> 4)) * PW2 + 8 * ((lid >> 3) & 1)) * 2);

    float acc = 0.0f;

    #pragma unroll 1
    for (int t = 0; t < TILES_PER_CTA; t++) {
        const int rowbase = grp * (TILES_PER_CTA * TILE_M) + t * TILE_M;

        // ---- cache X fragments for this warp's 16 rows (K=128: 32 regs) ----
        uint32_t xf[8][4];
        #pragma unroll
        for (int s = 0; s < 8; s++)
            LDSM4(xf[s], xlane + (uint32_t)(16 * s * 2));

        // ---- Phase A: GEMM1 in 16 n16-chunks, GELU -> register H ----
        // Hreg[s] is the m16k16 A-fragment for GEMM2 k-block s (R2-verified map).
        uint32_t Hreg[16][4];
        #pragma unroll
        for (int j = 0; j < 16; j++) {           // n16 chunk = h-cols 16j..16j+15
            float cA[4] = {0.f, 0.f, 0.f, 0.f};  // cols 16j+0..7
            float cB[4] = {0.f, 0.f, 0.f, 0.f};  // cols 16j+8..15
            #pragma unroll
            for (int s = 0; s < 8; s++) {
                uint32_t b[4];
                LDSM4(b, w1lane + (uint32_t)((16 * j * PW1 + 16 * s) * 2));
                MMA16816(cA, xf[s], b[0], b[1]);
                MMA16816(cB, xf[s], b[2], b[3]);
            }
            const float bb0 = b1s[16 * j + lc2];
            const float bb1 = b1s[16 * j + lc2 + 1];
            const float bb2 = b1s[16 * j + 8 + lc2];
            const float bb3 = b1s[16 * j + 8 + lc2 + 1];
            Hreg[j][0] = packbf2(gelu_fast(cA[0] + bb0), gelu_fast(cA[1] + bb1));
            Hreg[j][1] = packbf2(gelu_fast(cA[2] + bb0), gelu_fast(cA[3] + bb1));
            Hreg[j][2] = packbf2(gelu_fast(cB[0] + bb2), gelu_fast(cB[1] + bb3));
            Hreg[j][3] = packbf2(gelu_fast(cB[2] + bb2), gelu_fast(cB[3] + bb3));
        }

        __syncthreads();   // all warps done reading X smem

        // ---- overlap: stage next tile's X during phase B ----
        if (t + 1 < TILES_PER_CTA) {
            const int row0 = tid >> 5;
            const int col4 = (tid & 31) * 4;
            const float* gp = feat +
                ((size_t)(rowbase + TILE_M + row0) * NE + n) * EE + col4;
            char* sp = smem + OFF_X + (size_t)(row0 * PX + col4) * 2;
            #pragma unroll 8
            for (int it = 0; it < 16; it++) {
                float4 v = *(const float4*)(gp + (size_t)it * 16 * NE * EE);
                uint2 u;
                u.x = packbf2(v.x, v.y);
                u.y = packbf2(v.z, v.w);
                *reinterpret_cast<uint2*>(sp + (size_t)it * 16 * PX * 2) = u;
            }
        }

        // ---- Phase B: GEMM2 in 4 n32-chunks from register H; fused epilogue ----
        const int r0 = rowbase + 16 * wid + l4;
        const float* tg0 = tgt + ((size_t)r0 * NE + n) * EE;
        const float* tg1 = tg0 + (size_t)8 * NE * EE;
        #pragma unroll
        for (int q = 0; q < 4; q++) {            // e-cols 32q..32q+31
            float c2[4][4];
            #pragma unroll
            for (int i = 0; i < 4; i++)
                c2[i][0] = c2[i][1] = c2[i][2] = c2[i][3] = 0.f;

            #pragma unroll
            for (int s = 0; s < 16; s++) {
                #pragma unroll
                for (int tpp = 0; tpp < 2; tpp++) {
                    uint32_t b[4];
                    LDSM4(b, w2lane +
                          (uint32_t)(((32 * q + 16 * tpp) * PW2 + 16 * s) * 2));
                    MMA16816(c2[2 * tpp],     Hreg[s], b[0], b[1]);
                    MMA16816(c2[2 * tpp + 1], Hreg[s], b[2], b[3]);
                }
            }

            #pragma unroll
            for (int tp = 0; tp < 4; tp++) {
                const int e = 32 * q + 8 * tp + lc2;
                const float bb0 = b2s[e], bb1 = b2s[e + 1];
                float2 t0 = *(const float2*)(tg0 + e);
                float2 t1 = *(const float2*)(tg1 + e);
                float d0 = c2[tp][0] + bb0 - t0.x;
                float d1 = c2[tp][1] + bb1 - t0.y;
                float d2 = c2[tp][2] + bb0 - t1.x;
                float d3 = c2[tp][3] + bb1 - t1.y;
                acc += d0 * d0 + d1 * d1 + d2 * d2 + d3 * d3;
            }
        }

        __syncthreads();   // staged X visible; X buffer free next iteration
    }

    // ---- block reduction -> scaled atomic into d_out ----
    #pragma unroll
    for (int o = 16; o > 0; o >>= 1) acc += __shfl_down_sync(0xffffffffu, acc, o);
    float* red = (float*)(smem + OFF_RED);
    if (lid == 0) red[wid] = acc;
    __syncthreads();
    if (tid == 0) {
        float s = 0.f;
        #pragma unroll
        for (int i = 0; i < 16; i++) s += red[i];
        atomicAdd(out, s * (1.0f / 67108864.0f));   // / (B*NE*E)
    }
}

extern "C" void kernel_launch(void* const* d_in, const int* in_sizes, int n_in,
                              void* d_out, int out_size) {
    (void)in_sizes; (void)n_in; (void)out_size;
    const float* feat = (const float*)d_in[0];
    const float* tgt  = (const float*)d_in[1];
    const float* W1   = (const float*)d_in[2];
    const float* b1   = (const float*)d_in[3];
    const float* W2   = (const float*)d_in[4];
    const float* b2   = (const float*)d_in[5];

    cudaFuncSetAttribute(distill_kernel,
                         cudaFuncAttributeMaxDynamicSharedMemorySize, SMEM_TOTAL);
    init_out_kernel<<<1, 1>>>((float*)d_out);
    dim3 grid(NE, GROUPS);
    distill_kernel<<<grid, NTHREADS, SMEM_TOTAL>>>(feat, tgt, W1, b1, W2, b2,
                                                   (float*)d_out);
}

// round 7
// speedup vs baseline: 1.5082x; 1.0583x over previous
#include <cuda_runtime.h>
#include <cuda_bf16.h>
#include <cstdint>

// ---------------------------------------------------------------------------
// Problem constants
// ---------------------------------------------------------------------------
#define BB   16384
#define NE   32
#define EE   128
#define HH   256
#define TILE_M 256                 // 16 warps x M=16
#define TILES_PER_CTA 2
#define GROUPS 32
#define NTHREADS 512

// SMEM pitches (bf16 elements); pitch*2 bytes = odd multiple of 16B -> conflict-free
#define PX  136
#define PW1 136
#define PW2 264

#define OFF_X   0
#define SZ_X    (TILE_M * PX * 2)             // 69632
#define OFF_W1  (OFF_X + SZ_X)
#define SZ_W1   (HH * PW1 * 2)                // 69632
#define OFF_W2  (OFF_W1 + SZ_W1)
#define SZ_W2   (EE * PW2 * 2)                // 67584
#define OFF_B1  (OFF_W2 + SZ_W2)
#define OFF_B2  (OFF_B1 + HH * 4)
#define OFF_RED (OFF_B2 + EE * 4)
#define SMEM_TOTAL (OFF_RED + 16 * 4)         // ~208.5 KB

// ---------------------------------------------------------------------------
// Base-ISA PTX helpers (harness front-end is sm_103: no 'a' features)
// ---------------------------------------------------------------------------
static __device__ __forceinline__ uint32_t smem_u32(const void* p) {
    uint32_t a;
    asm("{ .reg .u64 t; cvta.to.shared.u64 t, %1; cvt.u32.u64 %0, t; }"
        : "=r"(a) : "l"(p));
    return a;
}

#define LDSM4(r, addr)                                                        \
    asm volatile("ldmatrix.sync.aligned.m8n8.x4.shared.b16 {%0,%1,%2,%3}, [%4];" \
                 : "=r"((r)[0]), "=r"((r)[1]), "=r"((r)[2]), "=r"((r)[3])      \
                 : "r"(addr))

#define MMA16816(c, a, b0, b1)                                                \
    asm volatile(                                                             \
        "mma.sync.aligned.m16n8k16.row.col.f32.bf16.bf16.f32 "                \
        "{%0,%1,%2,%3},{%4,%5,%6,%7},{%8,%9},{%0,%1,%2,%3};"                  \
        : "+f"((c)[0]), "+f"((c)[1]), "+f"((c)[2]), "+f"((c)[3])              \
        : "r"((a)[0]), "r"((a)[1]), "r"((a)[2]), "r"((a)[3]),                 \
          "r"(b0), "r"(b1))

// ---------------------------------------------------------------------------
static __device__ __forceinline__ float gelu_fast(float x) {
    float u = x * (0.7978845608f + 0.0356774081f * x * x);
    float t;
    asm("tanh.approx.f32 %0, %1;" : "=f"(t) : "f"(u));
    return 0.5f * x * (1.0f + t);
}

static __device__ __forceinline__ uint32_t packbf2(float lo, float hi) {
    __nv_bfloat162 p = __floats2bfloat162_rn(lo, hi);
    return *reinterpret_cast<uint32_t*>(&p);
}

__global__ void init_out_kernel(float* __restrict__ out) {
    out[0] = 0.0f;
}

__global__ __launch_bounds__(NTHREADS, 1)
void distill_kernel(const float* __restrict__ feat, const float* __restrict__ tgt,
                    const float* __restrict__ W1g, const float* __restrict__ b1g,
                    const float* __restrict__ W2g, const float* __restrict__ b2g,
                    float* __restrict__ out) {
    extern __shared__ char smem[];
    const uint32_t sb  = smem_u32(smem);
    const int tid = threadIdx.x;
    const int wid = tid >> 5;           // 0..15, warp owns rows 16*wid..+15
    const int lid = tid & 31;
    const int l4  = lid >> 2;
    const int lc2 = (lid & 3) * 2;
    const int n   = blockIdx.x;
    const int grp = blockIdx.y;

    float* b1s = (float*)(smem + OFF_B1);
    float* b2s = (float*)(smem + OFF_B2);

    // ---- one-time: weights fp32 -> bf16, transposed into SMEM ----
    {
        const float* w1 = W1g + (size_t)n * EE * HH;     // [k=128][h=256]
        #pragma unroll 4
        for (int f = tid; f < (EE * HH) / 4; f += NTHREADS) {
            int k  = f >> 6;
            int h4 = (f & 63) * 4;
            float4 v = *(const float4*)(w1 + k * HH + h4);
            __nv_bfloat16* base = (__nv_bfloat16*)(smem + OFF_W1) + k;
            base[(size_t)(h4 + 0) * PW1] = __float2bfloat16(v.x);
            base[(size_t)(h4 + 1) * PW1] = __float2bfloat16(v.y);
            base[(size_t)(h4 + 2) * PW1] = __float2bfloat16(v.z);
            base[(size_t)(h4 + 3) * PW1] = __float2bfloat16(v.w);
        }
        const float* w2 = W2g + (size_t)n * HH * EE;     // [h=256][e=128]
        #pragma unroll 4
        for (int f = tid; f < (HH * EE) / 4; f += NTHREADS) {
            int h  = f >> 5;
            int e4 = (f & 31) * 4;
            float4 v = *(const float4*)(w2 + h * EE + e4);
            __nv_bfloat16* base = (__nv_bfloat16*)(smem + OFF_W2) + h;
            base[(size_t)(e4 + 0) * PW2] = __float2bfloat16(v.x);
            base[(size_t)(e4 + 1) * PW2] = __float2bfloat16(v.y);
            base[(size_t)(e4 + 2) * PW2] = __float2bfloat16(v.z);
            base[(size_t)(e4 + 3) * PW2] = __float2bfloat16(v.w);
        }
        if (tid < HH) b1s[tid] = b1g[n * HH + tid];
        if (tid < EE) b2s[tid] = b2g[n * EE + tid];
    }

    // ---- stage X for tile 0 ----
    {
        const int row0 = tid >> 5;               // 0..15
        const int col4 = (tid & 31) * 4;
        const int rowbase = grp * (TILES_PER_CTA * TILE_M);
        const float* gp = feat + ((size_t)(rowbase + row0) * NE + n) * EE + col4;
        char* sp = smem + OFF_X + (size_t)(row0 * PX + col4) * 2;
        #pragma unroll 8
        for (int it = 0; it < 16; it++) {        // rows row0 + 16*it
            float4 v = *(const float4*)(gp + (size_t)it * 16 * NE * EE);
            uint2 u;
            u.x = packbf2(v.x, v.y);
            u.y = packbf2(v.z, v.w);
            *reinterpret_cast<uint2*>(sp + (size_t)it * 16 * PX * 2) = u;
        }
    }
    __syncthreads();

    // per-lane ldmatrix base addresses
    const uint32_t xlane = sb + OFF_X +
        (uint32_t)(((16 * wid + (lid & 15)) * PX + 8 * (lid >> 4)) * 2);
    const uint32_t w1lane = sb + OFF_W1 +
        (uint32_t)((((lid & 7) + 8 * (lid >> 4)) * PW1 + 8 * ((lid >> 3) & 1)) * 2);
    const uint32_t w2lane = sb + OFF_W2 +
        (uint32_t)((((lid & 7) + 8 * (lid >> 4)) * PW2 + 8 * ((lid >> 3) & 1)) * 2);

    float acc = 0.0f;

    #pragma unroll 1
    for (int t = 0; t < TILES_PER_CTA; t++) {
        const int rowbase = grp * (TILES_PER_CTA * TILE_M) + t * TILE_M;

        // ---- cache X fragments for this warp's 16 rows (K=128: 32 regs) ----
        uint32_t xf[8][4];
        #pragma unroll
        for (int s = 0; s < 8; s++)
            LDSM4(xf[s], xlane + (uint32_t)(16 * s * 2));
        __syncthreads();   // every warp has its X frags; X smem free after this

        // ---- fused k-streaming: per j, GEMM1 chunk -> GELU -> GEMM2 k-step ----
        // C2 accumulates full N=128: 16 independent n8 chains (64 regs).
        float c2[16][4];
        #pragma unroll
        for (int i = 0; i < 16; i++)
            c2[i][0] = c2[i][1] = c2[i][2] = c2[i][3] = 0.f;

        #pragma unroll 2
        for (int j = 0; j < 16; j++) {           // h-cols 16j..16j+15 = GEMM2 k-step j
            // GEMM1 chunk: C1[16 x 16] over K=128
            float cA[4] = {0.f, 0.f, 0.f, 0.f};
            float cB[4] = {0.f, 0.f, 0.f, 0.f};
            #pragma unroll
            for (int s = 0; s < 8; s++) {
                uint32_t b[4];
                LDSM4(b, w1lane + (uint32_t)((16 * j * PW1 + 16 * s) * 2));
                MMA16816(cA, xf[s], b[0], b[1]);
                MMA16816(cB, xf[s], b[2], b[3]);
            }
            // bias + GELU -> A-fragment for GEMM2 k-step j (transient)
            uint32_t h[4];
            {
                const float bb0 = b1s[16 * j + lc2];
                const float bb1 = b1s[16 * j + lc2 + 1];
                const float bb2 = b1s[16 * j + 8 + lc2];
                const float bb3 = b1s[16 * j + 8 + lc2 + 1];
                h[0] = packbf2(gelu_fast(cA[0] + bb0), gelu_fast(cA[1] + bb1));
                h[1] = packbf2(gelu_fast(cA[2] + bb0), gelu_fast(cA[3] + bb1));
                h[2] = packbf2(gelu_fast(cB[0] + bb2), gelu_fast(cB[1] + bb3));
                h[3] = packbf2(gelu_fast(cB[2] + bb2), gelu_fast(cB[3] + bb3));
            }
            // GEMM2 k-step j across all 128 e-cols: 16 independent chains
            #pragma unroll
            for (int tp = 0; tp < 8; tp++) {
                uint32_t b[4];
                LDSM4(b, w2lane + (uint32_t)((16 * tp * PW2 + 16 * j) * 2));
                MMA16816(c2[2 * tp],     h, b[0], b[1]);
                MMA16816(c2[2 * tp + 1], h, b[2], b[3]);
            }
        }

        // ---- overlap: stage next tile's X (X smem free since post-xf sync) ----
        if (t + 1 < TILES_PER_CTA) {
            const int row0 = tid >> 5;
            const int col4 = (tid & 31) * 4;
            const float* gp = feat +
                ((size_t)(rowbase + TILE_M + row0) * NE + n) * EE + col4;
            char* sp = smem + OFF_X + (size_t)(row0 * PX + col4) * 2;
            #pragma unroll 8
            for (int it = 0; it < 16; it++) {
                float4 v = *(const float4*)(gp + (size_t)it * 16 * NE * EE);
                uint2 u;
                u.x = packbf2(v.x, v.y);
                u.y = packbf2(v.z, v.w);
                *reinterpret_cast<uint2*>(sp + (size_t)it * 16 * PX * 2) = u;
            }
        }

        // ---- MSE epilogue (targets exact fp32 from GMEM) ----
        {
            const int r0 = rowbase + 16 * wid + l4;
            const float* tg0 = tgt + ((size_t)r0 * NE + n) * EE;
            const float* tg1 = tg0 + (size_t)8 * NE * EE;
            #pragma unroll
            for (int i = 0; i < 16; i++) {
                const int e = 8 * i + lc2;
                const float bb0 = b2s[e], bb1 = b2s[e + 1];
                float2 t0 = *(const float2*)(tg0 + e);
                float2 t1 = *(const float2*)(tg1 + e);
                float d0 = c2[i][0] + bb0 - t0.x;
                float d1 = c2[i][1] + bb1 - t0.y;
                float d2 = c2[i][2] + bb0 - t1.x;
                float d3 = c2[i][3] + bb1 - t1.y;
                acc += d0 * d0 + d1 * d1 + d2 * d2 + d3 * d3;
            }
        }

        __syncthreads();   // staged X visible before next tile's xf load
    }

    // ---- block reduction -> scaled atomic into d_out ----
    #pragma unroll
    for (int o = 16; o > 0; o >>= 1) acc += __shfl_down_sync(0xffffffffu, acc, o);
    float* red = (float*)(smem + OFF_RED);
    if (lid == 0) red[wid] = acc;
    __syncthreads();
    if (tid == 0) {
        float s = 0.f;
        #pragma unroll
        for (int i = 0; i < 16; i++) s += red[i];
        atomicAdd(out, s * (1.0f / 67108864.0f));   // / (B*NE*E)
    }
}

extern "C" void kernel_launch(void* const* d_in, const int* in_sizes, int n_in,
                              void* d_out, int out_size) {
    (void)in_sizes; (void)n_in; (void)out_size;
    const float* feat = (const float*)d_in[0];
    const float* tgt  = (const float*)d_in[1];
    const float* W1   = (const float*)d_in[2];
    const float* b1   = (const float*)d_in[3];
    const float* W2   = (const float*)d_in[4];
    const float* b2   = (const float*)d_in[5];

    cudaFuncSetAttribute(distill_kernel,
                         cudaFuncAttributeMaxDynamicSharedMemorySize, SMEM_TOTAL);
    init_out_kernel<<<1, 1>>>((float*)d_out);
    dim3 grid(NE, GROUPS);
    distill_kernel<<<grid, NTHREADS, SMEM_TOTAL>>>(feat, tgt, W1, b1, W2, b2,
                                                   (float*)d_out);
}